// round 17
// baseline (speedup 1.0000x reference)
#include <cuda_runtime.h>
#include <cstdint>

// Problem constants (fixed shapes for this problem instance)
#define B_ 32
#define T_ 10
#define P_ 25
#define H_ 100
#define W_ 100

#define NPTS      (B_ * T_ * P_)             // 8000 points
#define OUT_ELEMS (B_ * T_ * H_ * W_ * P_)   // 80,000,000 floats = 320 MB
#define OUT_VEC8  (OUT_ELEMS / 8)            // 10,000,000 32B granules

#define FILL_BLOCKS  1184                    // 148 SMs * 8
#define FILL_THREADS 1024

#define L1_WORDS (OUT_VEC8 / 32)             // 312,500  (1 bit / granule)
#define L2_WORDS (OUT_VEC8 / 4)              // 2,500,000 (1 byte / granule)

// Bitmaps. Static zero-init; the fill re-zeroes everything it consumes ->
// deterministic across graph replays.
__device__ uint32_t g_l1[L1_WORDS];
__device__ uint32_t g_l2[L2_WORDS];

// 256-bit streaming stores (sm_100+)
__device__ __forceinline__ void st_zero_256(float* p) {
    asm volatile(
        "st.global.cs.v8.f32 [%0], {%1, %1, %1, %1, %1, %1, %1, %1};"
        :: "l"(p), "f"(0.0f) : "memory");
}
__device__ __forceinline__ void st_val_256(float* p, const float* v) {
    asm volatile(
        "st.global.cs.v8.f32 [%0], {%1, %2, %3, %4, %5, %6, %7, %8};"
        :: "l"(p), "f"(v[0]), "f"(v[1]), "f"(v[2]), "f"(v[3]),
                   "f"(v[4]), "f"(v[5]), "f"(v[6]), "f"(v[7]) : "memory");
}

// ---------------------------------------------------------------------------
// Prepass: mark target elements. One thread per (b, t, p).
// Truncating (int) cast == astype(int32). Output slots never collide (each
// point owns a distinct innermost-p slot); bitmap word collisions use atomicOr.
// ---------------------------------------------------------------------------
__global__ void __launch_bounds__(128) set_bits_kernel(
        const float* __restrict__ x,
        const float* __restrict__ resolution,
        const float* __restrict__ origin) {
    int i = blockIdx.x * blockDim.x + threadIdx.x;
    if (i >= NPTS) return;

    int p  = i % P_;
    int bt = i / P_;          // b*T + t

    const float2 pxy = *(const float2*)(x + (size_t)bt * (2 * P_) + 2 * p);
    const float2 res = *(const float2*)(resolution + 2 * bt);
    const float2 org = *(const float2*)(origin + 2 * bt);

    int row = (int)(pxy.y / res.x + org.x);
    int col = (int)(pxy.x / res.y + org.y);

    if (row >= 0 && row < H_ && col >= 0 && col < W_) {
        uint32_t idx = ((((uint32_t)bt * H_ + row) * W_) + col) * P_ + p;  // < 80M
        uint32_t g = idx >> 3;          // granule
        uint32_t e = idx & 7;           // element within granule
        atomicOr(&g_l1[g >> 5], 1u << (g & 31));
        atomicOr(&g_l2[g >> 2], (1u << e) << ((g & 3) * 8));
    }
}

// ---------------------------------------------------------------------------
// Rare override path: NOINLINE so its registers never burden the hot loop
// (taken by <=8000 of 10M granules). Writes the merged 0/1 granule and
// re-zeroes the bitmap state it consumed.
// ---------------------------------------------------------------------------
__device__ __noinline__ void override_granule(float* __restrict__ outf,
                                              uint32_t g, uint32_t w) {
    unsigned lane = threadIdx.x & 31;
    uint8_t b = 0;
    if ((w >> lane) & 1u) {
        b = ((const uint8_t*)g_l2)[g];
    }
    float v[8];
#pragma unroll
    for (int e = 0; e < 8; e++) {
        v[e] = ((b >> e) & 1) ? 1.0f : 0.0f;
    }
    st_val_256(outf + 8 * (size_t)g, v);
    if (b) {                            // clear per-granule byte (no race: distinct bytes)
        ((uint8_t*)g_l2)[g] = 0;
    }
    if (lane == 0) {                    // word exclusive to this warp's batch
        g_l1[g >> 5] = 0;
    }
}

// ---------------------------------------------------------------------------
// Fill-with-override. __launch_bounds__(1024, 2) forces <=32 regs/thread so
// 2 CTAs/SM stay resident (R15 had regs=43 -> 1 CTA/SM -> 5.0 TB/s).
// 32-bit granule indexing; per-granule: one warp-broadcast bitmap load and a
// warp-uniform w==0 test (true for ~99.92% of granules) guarding a pure
// streaming zero store. PDL secondary: gridsync at the top orders the
// prepass's bitmap writes while hiding this kernel's launch latency.
// ---------------------------------------------------------------------------
__global__ void __launch_bounds__(FILL_THREADS, 2) fill_apply_kernel(float* __restrict__ outf) {
    cudaGridDependencySynchronize();    // wait for set_bits' bitmap writes

    const uint32_t stride = FILL_BLOCKS * FILL_THREADS;            // 1,212,416
    uint32_t i = blockIdx.x * FILL_THREADS + threadIdx.x;

    const uint32_t end8 = OUT_VEC8 - 7u * stride;                  // 1,513,088
    if (i < end8) {
#pragma unroll
        for (int u = 0; u < 8; u++) {
            uint32_t g = i + (uint32_t)u * stride;
            uint32_t w = g_l1[g >> 5];
            if (w == 0) {
                st_zero_256(outf + 8 * (size_t)g);
            } else {
                override_granule(outf, g, w);
            }
        }
        i += 8u * stride;
    }
    for (; i < (uint32_t)OUT_VEC8; i += stride) {
        uint32_t w = g_l1[i >> 5];
        if (w == 0) {
            st_zero_256(outf + 8 * (size_t)i);
        } else {
            override_granule(outf, i, w);
        }
    }
}

extern "C" void kernel_launch(void* const* d_in, const int* in_sizes, int n_in,
                              void* d_out, int out_size) {
    const float* x          = (const float*)d_in[0];
    const float* resolution = (const float*)d_in[1];
    const float* origin     = (const float*)d_in[2];
    float* out = (float*)d_out;

    // 1) mark the <=8000 target elements in the bitmaps
    {
        const int threads = 128;
        const int blocks  = (NPTS + threads - 1) / threads;  // 63
        set_bits_kernel<<<blocks, threads>>>(x, resolution, origin);
    }

    // 2) fill 320MB with zeros + merged 1.0f overrides
    {
        cudaLaunchConfig_t cfg = {};
        cfg.gridDim  = dim3(FILL_BLOCKS);
        cfg.blockDim = dim3(FILL_THREADS);
        cfg.dynamicSmemBytes = 0;
        cfg.stream = 0;

        cudaLaunchAttribute attrs[1];
        attrs[0].id = cudaLaunchAttributeProgrammaticStreamSerialization;
        attrs[0].val.programmaticStreamSerializationAllowed = 1;
        cfg.attrs = attrs;
        cfg.numAttrs = 1;

        cudaLaunchKernelEx(&cfg, fill_apply_kernel, out);
    }
}